// round 7
// baseline (speedup 1.0000x reference)
#include <cuda_runtime.h>

// context_window: out[b, f*11 + c, t] = x[b, f, t + c - 5], zero-padded in t.
// x: (32, 80, 3000) fp32 -> out: (32, 880, 3000) fp32.
//
// R7: output-centric gather with a FULLY LINEAR write stream.
// Grid y = output channel (b*880 + f*11 + c, 28160 total); each CTA writes a
// contiguous chunk of one 12KB output channel, consecutive CTAs -> consecutive
// memory. Per thread: shift s = c-5 is CTA-uniform; load two aligned float4s
// covering x[t+4q .. t+4q+7] (q = s>>2) and select the 4-float window by the
// uniform remainder r = s&3 (static 4-way switch, no misaligned vectors).
// Tests whether DRAM write page/bank locality (vs 12KB-strided scatter) is
// the missing ~30% of write bandwidth.

#define T_DIM   3000
#define C_LEN   11
#define T4      (T_DIM / 4)     // 750
#define OUTCH   (32 * 880)      // 28160 output channels

__global__ __launch_bounds__(256) void context_window_kernel(
    const float* __restrict__ x, float* __restrict__ out)
{
    int t4 = blockIdx.x * blockDim.x + threadIdx.x;
    if (t4 >= T4) return;
    int och = blockIdx.y;                 // b*880 + f*11 + c

    // Decompose output channel (divisions by constants -> mul/shift).
    int b   = och / 880;
    int rem = och - b * 880;
    int f   = rem / C_LEN;
    int c   = rem - f * C_LEN;

    const float* __restrict__ xr = x + (b * 80 + f) * T_DIM;
    int t = t4 * 4;
    int s = c - 5;                        // shift in [-5, 5], CTA-uniform

    float o0, o1, o2, o3;

    if (t4 >= 2 && t4 <= T4 - 3) {
        // Interior: two aligned float4 loads covering x[t+4q .. t+4q+7].
        // q in [-2, 1] -> addresses within [t-8, t+11], in-range for t4 in [2, 747].
        int q = s >> 2;                   // arithmetic floor
        int r = s & 3;
        const float4* __restrict__ p =
            reinterpret_cast<const float4*>(xr + t) + q;
        float4 w0 = __ldg(p);
        float4 w1 = __ldg(p + 1);
        // o[j] = element (r + j) of concat(w0, w1); r is warp-uniform.
        switch (r) {
            case 0: o0 = w0.x; o1 = w0.y; o2 = w0.z; o3 = w0.w; break;
            case 1: o0 = w0.y; o1 = w0.z; o2 = w0.w; o3 = w1.x; break;
            case 2: o0 = w0.z; o1 = w0.w; o2 = w1.x; o3 = w1.y; break;
            default: o0 = w0.w; o1 = w1.x; o2 = w1.y; o3 = w1.z; break;
        }
    } else {
        // Edge chunks (t4 in {0,1,748,749}): scalar bounds-checked loads
        // (implements the zero padding).
        float tmp[4];
        #pragma unroll
        for (int j = 0; j < 4; j++) {
            int idx = t + s + j;
            tmp[j] = (idx >= 0 && idx < T_DIM) ? xr[idx] : 0.0f;
        }
        o0 = tmp[0]; o1 = tmp[1]; o2 = tmp[2]; o3 = tmp[3];
    }

    // Linear write stream: channel och, offset t. Warp-wide 512B contiguous;
    // consecutive CTAs write consecutive 12KB channel segments.
    *reinterpret_cast<float4*>(out + och * T_DIM + t) =
        make_float4(o0, o1, o2, o3);
}

extern "C" void kernel_launch(void* const* d_in, const int* in_sizes, int n_in,
                              void* d_out, int out_size)
{
    const float* x = (const float*)d_in[0];
    float* out = (float*)d_out;

    dim3 block(256);
    dim3 grid((T4 + 255) / 256, OUTCH);   // (3, 28160)
    context_window_kernel<<<grid, block>>>(x, out);
}

// round 8
// speedup vs baseline: 1.5051x; 1.5051x over previous
#include <cuda_runtime.h>

// context_window: out[b, f*11 + c, t] = x[b, f, t + c - 5], zero-padded in t.
// x: (32, 80, 3000) fp32 -> out: (32, 880, 3000) fp32.
//
// R8: R1 data path (5 aligned LDG.128 window -> 11 contiguous STG.128, the
// proven-at-roofline shape: 368.6MB / 55.3us = 6.67TB/s = 83% of spec), with
// the remaining slack trimmed:
//  - exact 1D launch: 2560 rows x 750 t4 = 1,920,000 threads = 7500 x 256,
//    zero idle threads (R1 wasted 2.3% in padded grid.x)
//  - default stores (.cs hint measured neutral-to-worse in R3/R4)

#define T_DIM   3000
#define C_LEN   11
#define ROWS    (32 * 80)        // 2560
#define T4      (T_DIM / 4)      // 750
#define NWORK   (ROWS * T4)      // 1,920,000
#define BLOCK   256
#define GRID    (NWORK / BLOCK)  // 7500 exactly

__global__ __launch_bounds__(BLOCK) void context_window_kernel(
    const float* __restrict__ x, float* __restrict__ out)
{
    int tid = blockIdx.x * BLOCK + threadIdx.x;   // < NWORK by construction
    int row = tid / T4;                           // b*80 + f (mul-shift)
    int t4  = tid - row * T4;
    int t   = t4 * 4;

    const float* __restrict__ xr = x + row * T_DIM;

    // Register window w[k] = x[t-8+k], k = 0..19.
    // out[c, t+j] = x[t + j + c - 5] = w[j + c + 3]; used range w[3..16].
    float w[20];

    if (t4 >= 2 && t4 <= T4 - 3) {
        // Fast path: 5 aligned float4 loads, fully in-range.
        const float4* __restrict__ p = reinterpret_cast<const float4*>(xr + t - 8);
        #pragma unroll
        for (int i = 0; i < 5; i++) {
            float4 v = p[i];
            w[4*i + 0] = v.x; w[4*i + 1] = v.y;
            w[4*i + 2] = v.z; w[4*i + 3] = v.w;
        }
    } else {
        // Edge path (t4 in {0,1,748,749}): scalar bounds-checked loads
        // (implements the zero padding).
        #pragma unroll
        for (int k = 0; k < 20; k++) {
            int idx = t - 8 + k;
            w[k] = (idx >= 0 && idx < T_DIM) ? xr[idx] : 0.0f;
        }
    }

    // 11 coalesced, aligned float4 stores — one per context shift.
    float* __restrict__ orow = out + (row * C_LEN) * T_DIM + t;
    #pragma unroll
    for (int c = 0; c < C_LEN; c++) {
        *reinterpret_cast<float4*>(orow + c * T_DIM) =
            make_float4(w[c + 3], w[c + 4], w[c + 5], w[c + 6]);
    }
}

extern "C" void kernel_launch(void* const* d_in, const int* in_sizes, int n_in,
                              void* d_out, int out_size)
{
    const float* x = (const float*)d_in[0];
    float* out = (float*)d_out;

    context_window_kernel<<<GRID, BLOCK>>>(x, out);
}

// round 9
// speedup vs baseline: 1.5190x; 1.0092x over previous
#include <cuda_runtime.h>

// context_window: out[b, f*11 + c, t] = x[b, f, t + c - 5], zero-padded in t.
// x: (32, 80, 3000) fp32 -> out: (32, 880, 3000) fp32.
//
// R9: R1 data path (proven ~83% of HBM spec), with the load schedule
// INTERLEAVED into the store burst and pinned via volatile inline asm.
// Rationale (B300_MICROARCH "Multi-CTA spread"): per-CTA completion spread at
// occ>=8 grows with MLP_p1 = # of consecutive front-batched LDGs in SASS
// (cross-CTA L1tex-queue contention). ptxas hoists all 5 window loads ->
// MLP_p1=5 -> predicted spread ~1.4x. Interleaving gives MLP_p1=2 ->
// spread ~ 1.1x floor. Schedule:
//   ld p0,p1 | st c0 | ld p2 | st c1..4 | ld p3 | st c5..8 | ld p4 | st c9,c10

#define T_DIM   3000
#define C_LEN   11
#define ROWS    (32 * 80)     // 2560
#define T4      (T_DIM / 4)   // 750

__device__ __forceinline__ float4 ldg128(const float* p) {
    float4 v;
    asm volatile("ld.global.nc.v4.f32 {%0,%1,%2,%3}, [%4];"
                 : "=f"(v.x), "=f"(v.y), "=f"(v.z), "=f"(v.w) : "l"(p));
    return v;
}

__device__ __forceinline__ void stg128(float* p, float a, float b, float c, float d) {
    asm volatile("st.global.v4.f32 [%0], {%1,%2,%3,%4};"
                 :: "l"(p), "f"(a), "f"(b), "f"(c), "f"(d) : "memory");
}

__global__ __launch_bounds__(256) void context_window_kernel(
    const float* __restrict__ x, float* __restrict__ out)
{
    int t4 = blockIdx.x * blockDim.x + threadIdx.x;
    if (t4 >= T4) return;
    int row = blockIdx.y;                 // b*80 + f
    int t = t4 * 4;

    const float* __restrict__ xr = x + row * T_DIM;
    float* __restrict__ orow = out + (row * C_LEN) * T_DIM + t;

    // Window w[k] = x[t-8+k]; out[c, t+j] = w[j + c + 3].
    // p_i covers w[4i .. 4i+3]; store c needs w[c+3 .. c+6].

    if (t4 >= 2 && t4 <= T4 - 3) {
        const float* base = xr + t - 8;

        // MLP_p1 = 2: only p0,p1 front-batched; later loads interleaved
        // between the stores they feed (order pinned by volatile asm).
        float4 p0 = ldg128(base +  0);        // w0..3
        float4 p1 = ldg128(base +  4);        // w4..7
        stg128(orow + 0 * T_DIM, p0.w, p1.x, p1.y, p1.z);          // c=0: w3..6

        float4 p2 = ldg128(base +  8);        // w8..11
        stg128(orow + 1 * T_DIM, p1.x, p1.y, p1.z, p1.w);          // c=1: w4..7
        stg128(orow + 2 * T_DIM, p1.y, p1.z, p1.w, p2.x);          // c=2: w5..8
        stg128(orow + 3 * T_DIM, p1.z, p1.w, p2.x, p2.y);          // c=3: w6..9
        stg128(orow + 4 * T_DIM, p1.w, p2.x, p2.y, p2.z);          // c=4: w7..10

        float4 p3 = ldg128(base + 12);        // w12..15
        stg128(orow + 5 * T_DIM, p2.x, p2.y, p2.z, p2.w);          // c=5: w8..11
        stg128(orow + 6 * T_DIM, p2.y, p2.z, p2.w, p3.x);          // c=6: w9..12
        stg128(orow + 7 * T_DIM, p2.z, p2.w, p3.x, p3.y);          // c=7: w10..13
        stg128(orow + 8 * T_DIM, p2.w, p3.x, p3.y, p3.z);          // c=8: w11..14

        float4 p4 = ldg128(base + 16);        // w16..19
        stg128(orow +  9 * T_DIM, p3.x, p3.y, p3.z, p3.w);         // c=9: w12..15
        stg128(orow + 10 * T_DIM, p3.y, p3.z, p3.w, p4.x);         // c=10: w13..16
    } else {
        // Edge path (t4 in {0,1,748,749}): scalar bounds-checked loads
        // (implements the zero padding).
        float w[20];
        #pragma unroll
        for (int k = 0; k < 20; k++) {
            int idx = t - 8 + k;
            w[k] = (idx >= 0 && idx < T_DIM) ? xr[idx] : 0.0f;
        }
        #pragma unroll
        for (int c = 0; c < C_LEN; c++) {
            stg128(orow + c * T_DIM, w[c + 3], w[c + 4], w[c + 5], w[c + 6]);
        }
    }
}

extern "C" void kernel_launch(void* const* d_in, const int* in_sizes, int n_in,
                              void* d_out, int out_size)
{
    const float* x = (const float*)d_in[0];
    float* out = (float*)d_out;

    dim3 block(256);
    dim3 grid((T4 + 255) / 256, ROWS);   // (3, 2560)
    context_window_kernel<<<grid, block>>>(x, out);
}

// round 10
// speedup vs baseline: 1.5315x; 1.0082x over previous
#include <cuda_runtime.h>

// context_window: out[b, f*11 + c, t] = x[b, f, t + c - 5], zero-padded in t.
// x: (32, 80, 3000) fp32 -> out: (32, 880, 3000) fp32.
//
// FINAL (R10): consolidation at the measured roofline.
// Nine design variants (tile width 4/8, .cs streaming stores, shuffle-built
// windows, persistent grid, 256-bit LDG/STG, output-centric gather, exact 1D
// grid, asm-pinned load/store interleave) all measured 55.3-57.8us ncu-side
// with DRAM 68-71%: the kernel is bound by the compulsory 338MB write +
// 31MB read stream at ~6.7TB/s (~83% of HBM3e spec). This is the
// best-measured shape: per thread, 5 aligned LDG.128 covering the 20-float
// window x[t-8..t+11], then 11 warp-contiguous STG.128 (one per context
// shift), default cache policy.

#define T_DIM   3000
#define C_LEN   11
#define ROWS    (32 * 80)     // B*F = 2560
#define T4      (T_DIM / 4)   // 750 float4 chunks per row

__global__ __launch_bounds__(256) void context_window_kernel(
    const float* __restrict__ x, float* __restrict__ out)
{
    int t4 = blockIdx.x * blockDim.x + threadIdx.x;
    if (t4 >= T4) return;
    int row = blockIdx.y;                 // b*80 + f
    int t = t4 * 4;

    const float* __restrict__ xr = x + row * T_DIM;

    // Register window covering x[t-8 .. t+11] (w[k] = x[t-8+k]).
    // out[c, t+j] = x[t + j + c - 5] = w[j + c + 3]; used range w[3..16].
    float w[20];

    if (t4 >= 2 && t4 <= T4 - 3) {
        // Fast path: 5 aligned float4 loads, fully in-range.
        const float4* __restrict__ p = reinterpret_cast<const float4*>(xr + t - 8);
        #pragma unroll
        for (int i = 0; i < 5; i++) {
            float4 v = p[i];
            w[4*i + 0] = v.x; w[4*i + 1] = v.y;
            w[4*i + 2] = v.z; w[4*i + 3] = v.w;
        }
    } else {
        // Edge path (t4 in {0,1,748,749}): scalar bounds-checked loads
        // (implements the zero padding).
        #pragma unroll
        for (int k = 0; k < 20; k++) {
            int idx = t - 8 + k;
            w[k] = (idx >= 0 && idx < T_DIM) ? xr[idx] : 0.0f;
        }
    }

    // 11 coalesced, aligned float4 stores — one per context shift.
    // Warp-wide each store is 512B fully contiguous.
    float* __restrict__ orow = out + (row * C_LEN) * T_DIM + t;
    #pragma unroll
    for (int c = 0; c < C_LEN; c++) {
        *reinterpret_cast<float4*>(orow + c * T_DIM) =
            make_float4(w[c + 3], w[c + 4], w[c + 5], w[c + 6]);
    }
}

extern "C" void kernel_launch(void* const* d_in, const int* in_sizes, int n_in,
                              void* d_out, int out_size)
{
    const float* x = (const float*)d_in[0];
    float* out = (float*)d_out;

    dim3 block(256);
    dim3 grid((T4 + 255) / 256, ROWS);   // (3, 2560)
    context_window_kernel<<<grid, block>>>(x, out);
}